// round 16
// baseline (speedup 1.0000x reference)
#include <cuda_runtime.h>
#include <cuda_fp16.h>
#include <cstdint>

#define MAX_N 100000
#define MAX_E 1600000

// Scratch (device globals: no allocation allowed)
__device__ __half g_h[(size_t)MAX_N * 64];   // dis-scaled post-GEMM features (fp16)
__device__ __half g_y[(size_t)MAX_N * 64];   // aggregated features (fp16)
__device__ int    g_deg[MAX_N];              // in-degree (excl self loop)
__device__ float  g_dis[MAX_N];              // rsqrt(deg+1)
__device__ int    g_offs[MAX_N];             // CSR row offsets
__device__ int    g_cursor[MAX_N];           // fill cursors
__device__ int    g_nbr[MAX_E];              // src ids sorted by dst
__device__ int    g_bsum[256];               // block sums for scan

// ---------------------------------------------------------------------------
// degree
// ---------------------------------------------------------------------------
__global__ void degree_kernel(const int* __restrict__ dst, int E, int* __restrict__ deg) {
    int e = blockIdx.x * blockDim.x + threadIdx.x;
    if (e < E) atomicAdd(&deg[dst[e]], 1);
}

// ---------------------------------------------------------------------------
// prefix scan of deg -> offs (1024 elems / block), fused dis = rsqrt(deg+1)
// ---------------------------------------------------------------------------
__global__ __launch_bounds__(256)
void scan1_kernel(const int* __restrict__ deg, int n,
                  int* __restrict__ offs, int* __restrict__ bsum,
                  float* __restrict__ dis)
{
    __shared__ int warp_sums[8];
    const int base = blockIdx.x * 1024;
    const int tid = threadIdx.x;
    int v[4];
    int s = 0;
#pragma unroll
    for (int i = 0; i < 4; i++) {
        int idx = base + tid * 4 + i;
        v[i] = (idx < n) ? deg[idx] : 0;
        if (idx < n) dis[idx] = rsqrtf((float)v[i] + 1.0f);
        s += v[i];
    }
    const int lane = tid & 31, wid = tid >> 5;
    int ps = s;
#pragma unroll
    for (int d = 1; d < 32; d <<= 1) {
        int t = __shfl_up_sync(~0u, ps, d);
        if (lane >= d) ps += t;
    }
    if (lane == 31) warp_sums[wid] = ps;
    __syncthreads();
    if (tid < 8) {
        int w = warp_sums[tid];
#pragma unroll
        for (int d = 1; d < 8; d <<= 1) {
            int t = __shfl_up_sync(0xffu, w, d);
            if (tid >= d) w += t;
        }
        warp_sums[tid] = w;
    }
    __syncthreads();
    int thread_excl = (wid > 0 ? warp_sums[wid - 1] : 0) + (ps - s);
    int run = thread_excl;
#pragma unroll
    for (int i = 0; i < 4; i++) {
        int idx = base + tid * 4 + i;
        if (idx < n) offs[idx] = run;
        run += v[i];
    }
    if (tid == 255) bsum[blockIdx.x] = thread_excl + s;
}

// ---------------------------------------------------------------------------
// scan3: finalize offs/cursor (redundant per-block scan of <=128 block sums)
// ---------------------------------------------------------------------------
__global__ __launch_bounds__(256)
void scan3_kernel(int* __restrict__ offs, int* __restrict__ cursor,
                  const int* __restrict__ bsum, int n, int nb)
{
    __shared__ int sb[128];
    __shared__ int wsum[4];
    const int tid = threadIdx.x;

    int v = 0, ps = 0;
    const int lane = tid & 31, w = tid >> 5;
    if (tid < 128) {
        v = (tid < nb) ? bsum[tid] : 0;
        ps = v;
#pragma unroll
        for (int d = 1; d < 32; d <<= 1) {
            int t = __shfl_up_sync(~0u, ps, d);
            if (lane >= d) ps += t;
        }
        if (lane == 31) wsum[w] = ps;
    }
    __syncthreads();
    if (tid < 4) {
        int x = wsum[tid];
#pragma unroll
        for (int d = 1; d < 4; d <<= 1) {
            int t = __shfl_up_sync(0xfu, x, d);
            if (tid >= d) x += t;
        }
        wsum[tid] = x;
    }
    __syncthreads();
    if (tid < 128) {
        sb[tid] = (ps - v) + (w > 0 ? wsum[w - 1] : 0);   // exclusive prefix
    }
    __syncthreads();

    int i = blockIdx.x * blockDim.x + tid;
    if (i < n) {
        int o = offs[i] + sb[i >> 10];
        offs[i] = o;
        cursor[i] = o;
    }
}

__global__ void fill_kernel(const int* __restrict__ src, const int* __restrict__ dst,
                            int E, int* __restrict__ cursor, int* __restrict__ nbr)
{
    int e = blockIdx.x * blockDim.x + threadIdx.x;
    if (e < E) {
        int d = dst[e];
        int p = atomicAdd(&cursor[d], 1);
        nbr[p] = src[e];
    }
}

// ---------------------------------------------------------------------------
// FP16 tensor-core GEMM (mma.m16n8k16, fp32 accumulate), relu-on-load,
// dis-scale + fp16 epilogue, SOFTWARE-PIPELINED X loads:
//   prefetch chunk k+1's X into registers right after the stage-sync,
//   so its DRAM latency hides behind the mma phase + tail sync.
// W staged fp16 TRANSPOSED (k-contig, stride 40 halves, conflict-free).
// ---------------------------------------------------------------------------
__device__ __forceinline__ void mma_f16(float* c, const uint32_t* a,
                                        uint32_t b0, uint32_t b1) {
    asm volatile(
        "mma.sync.aligned.m16n8k16.row.col.f32.f16.f16.f32 "
        "{%0,%1,%2,%3}, {%4,%5,%6,%7}, {%8,%9}, {%0,%1,%2,%3};"
        : "+f"(c[0]), "+f"(c[1]), "+f"(c[2]), "+f"(c[3])
        : "r"(a[0]), "r"(a[1]), "r"(a[2]), "r"(a[3]), "r"(b0), "r"(b1));
}

template <int K, int M, bool RELU, typename XT>
__global__ __launch_bounds__(256)
void gemm_f16(const XT* __restrict__ X, const float* __restrict__ W,
              const float* __restrict__ dis, __half* __restrict__ H, int n)
{
    constexpr bool HALF_IN = (sizeof(XT) == 2);
    constexpr int BM = 128, BK = 32;
    constexpr int XSTR = BK + 8;     // 40 halves (20 b32)
    constexpr int WTSTR = BK + 8;    // wt[M][BK] stride, 40 halves
    constexpr int NB = M / 8;
    constexpr int NCH = K / BK;      // chunks (4 for K=128, 2 for K=64)

    extern __shared__ __half smemh[];
    __half* xs = smemh;                     // BM * XSTR halves
    __half* wt = smemh + BM * XSTR;         // M * WTSTR halves (transposed W)

    const int tid  = threadIdx.x;
    const int lane = tid & 31;
    const int warp = tid >> 5;
    const int row0 = blockIdx.x * BM;
    const int wrow = warp * 16;
    const int g = lane >> 2;
    const int t = lane & 3;

    float acc[NB][4];
#pragma unroll
    for (int nb = 0; nb < NB; nb++)
#pragma unroll
        for (int c = 0; c < 4; c++) acc[nb][c] = 0.f;

    // prefetch registers
    float4 xf[4];   // fp32 input path (4 rounds)
    uint4  xh[2];   // fp16 input path (2 rounds)

    // --- prologue: load chunk 0 into registers ---
    if (HALF_IN) {
#pragma unroll
        for (int round = 0; round < 2; round++) {
            int r = (tid >> 2) + round * 64;
            int row = row0 + r;
            int koff = (tid & 3) * 8;
            xh[round] = make_uint4(0u, 0u, 0u, 0u);
            if (row < n)
                xh[round] = *(const uint4*)((const __half*)X + (size_t)row * K + koff);
        }
    } else {
#pragma unroll
        for (int round = 0; round < 4; round++) {
            int r = (tid >> 3) + round * 32;
            int row = row0 + r;
            int koff = (tid & 7) * 4;
            xf[round] = make_float4(0.f, 0.f, 0.f, 0.f);
            if (row < n)
                xf[round] = *(const float4*)((const float*)X + (size_t)row * K + koff);
        }
    }

    for (int it = 0; it < NCH; it++) {
        const int k0 = it * BK;
        // --- store prefetched X chunk to smem (convert / relu) ---
        if (HALF_IN) {
            const __half2 z2 = __floats2half2_rn(0.f, 0.f);
#pragma unroll
            for (int round = 0; round < 2; round++) {
                int r = (tid >> 2) + round * 64;
                int koff = (tid & 3) * 8;
                uint4 raw = xh[round];
                if (RELU) {
                    __half2* h2 = (__half2*)&raw;
#pragma unroll
                    for (int q = 0; q < 4; q++) h2[q] = __hmax2(h2[q], z2);
                }
                *(uint4*)&xs[r * XSTR + koff] = raw;
            }
        } else {
#pragma unroll
            for (int round = 0; round < 4; round++) {
                int r = (tid >> 3) + round * 32;
                int koff = (tid & 7) * 4;
                float4 v = xf[round];
                if (RELU) {
                    v.x = fmaxf(v.x, 0.f); v.y = fmaxf(v.y, 0.f);
                    v.z = fmaxf(v.z, 0.f); v.w = fmaxf(v.w, 0.f);
                }
                __half2 p0 = __floats2half2_rn(v.x, v.y);
                __half2 p1 = __floats2half2_rn(v.z, v.w);
                uint2 pk = make_uint2(*(uint32_t*)&p0, *(uint32_t*)&p1);
                *(uint2*)&xs[r * XSTR + koff] = pk;
            }
        }
        // --- stage W chunk TRANSPOSED (L2-hot: same 32KB for every block) ---
#pragma unroll
        for (int i = tid * 4; i < BK * M; i += 1024) {
            int kk = i / M, m = i % M;
            float4 v = *(const float4*)(W + (size_t)(k0 + kk) * M + m);
            wt[(m + 0) * WTSTR + kk] = __float2half_rn(v.x);
            wt[(m + 1) * WTSTR + kk] = __float2half_rn(v.y);
            wt[(m + 2) * WTSTR + kk] = __float2half_rn(v.z);
            wt[(m + 3) * WTSTR + kk] = __float2half_rn(v.w);
        }
        __syncthreads();

        // --- prefetch NEXT chunk's X into registers (hide DRAM latency) ---
        if (it + 1 < NCH) {
            const int kn = k0 + BK;
            if (HALF_IN) {
#pragma unroll
                for (int round = 0; round < 2; round++) {
                    int r = (tid >> 2) + round * 64;
                    int row = row0 + r;
                    int koff = (tid & 3) * 8;
                    xh[round] = make_uint4(0u, 0u, 0u, 0u);
                    if (row < n)
                        xh[round] = *(const uint4*)((const __half*)X + (size_t)row * K + kn + koff);
                }
            } else {
#pragma unroll
                for (int round = 0; round < 4; round++) {
                    int r = (tid >> 3) + round * 32;
                    int row = row0 + r;
                    int koff = (tid & 7) * 4;
                    xf[round] = make_float4(0.f, 0.f, 0.f, 0.f);
                    if (row < n)
                        xf[round] = *(const float4*)((const float*)X + (size_t)row * K + kn + koff);
                }
            }
        }

        // --- mma phase ---
#pragma unroll
        for (int ks = 0; ks < BK / 16; ks++) {
            const uint32_t* xp = (const uint32_t*)xs;
            const uint32_t* wp = (const uint32_t*)wt;
            uint32_t a[4];
            {
                int ib = (wrow + g) * (XSTR / 2) + ks * 8 + t;
                a[0] = xp[ib];
                a[1] = xp[ib + 8 * (XSTR / 2)];
                a[2] = xp[ib + 4];
                a[3] = xp[ib + 8 * (XSTR / 2) + 4];
            }
#pragma unroll
            for (int nb = 0; nb < NB; nb++) {
                const int nn = nb * 8 + g;
                int jb = nn * (WTSTR / 2) + ks * 8 + t;
                uint32_t b0 = wp[jb];
                uint32_t b1 = wp[jb + 4];
                mma_f16(acc[nb], a, b0, b1);
            }
        }
        __syncthreads();
    }

    // epilogue: scale by dis[row], convert fp16, store
    const int rA = row0 + wrow + g;
    const int rB = rA + 8;
    const float sA = (rA < n) ? dis[rA] : 0.f;
    const float sB = (rB < n) ? dis[rB] : 0.f;
#pragma unroll
    for (int nb = 0; nb < NB; nb++) {
        int colo = nb * 8 + 2 * t;
        if (rA < n) {
            __half2 p = __floats2half2_rn(acc[nb][0] * sA, acc[nb][1] * sA);
            *(__half2*)(H + (size_t)rA * M + colo) = p;
        }
        if (rB < n) {
            __half2 p = __floats2half2_rn(acc[nb][2] * sB, acc[nb][3] * sB);
            *(__half2*)(H + (size_t)rB * M + colo) = p;
        }
    }
}

// ---------------------------------------------------------------------------
// pull-style CSR aggregation (fp16 gather, fp32 accumulate):
//   y[d,:] = dis[d] * ( h[d,:] + sum_{s in N(d)} h[s,:] ) + b[:]
// D/8 threads per node; 4-deep neighbor unroll (proven best: R9)
// ---------------------------------------------------------------------------
__device__ __forceinline__ void acc_row8(float* acc, const __half* p) {
    uint4 raw = *(const uint4*)p;
    const __half2* h2 = (const __half2*)&raw;
#pragma unroll
    for (int q = 0; q < 4; q++) {
        float2 f = __half22float2(h2[q]);
        acc[q * 2 + 0] += f.x;
        acc[q * 2 + 1] += f.y;
    }
}

template <int D, bool OUT_HALF>
__global__ __launch_bounds__(256)
void aggregate_kernel(const __half* __restrict__ h,
                      const int* __restrict__ offs,
                      const int* __restrict__ deg,
                      const int* __restrict__ nbr,
                      const float* __restrict__ dis,
                      const float* __restrict__ bias,
                      void* __restrict__ y_out, int n)
{
    constexpr int TPN = D / 8;
    int gid = blockIdx.x * blockDim.x + threadIdx.x;
    int node = gid / TPN;
    int lane = gid % TPN;
    if (node >= n) return;
    const int col = lane * 8;
    const int start = offs[node];
    const int cnt = deg[node];

    float acc[8];
    {
        uint4 raw = *(const uint4*)(h + (size_t)node * D + col);
        const __half2* h2 = (const __half2*)&raw;
#pragma unroll
        for (int q = 0; q < 4; q++) {
            float2 f = __half22float2(h2[q]);
            acc[q * 2 + 0] = f.x;
            acc[q * 2 + 1] = f.y;
        }
    }

    int j = 0;
    for (; j + 4 <= cnt; j += 4) {
        int s0 = nbr[start + j + 0];
        int s1 = nbr[start + j + 1];
        int s2 = nbr[start + j + 2];
        int s3 = nbr[start + j + 3];
        acc_row8(acc, h + (size_t)s0 * D + col);
        acc_row8(acc, h + (size_t)s1 * D + col);
        acc_row8(acc, h + (size_t)s2 * D + col);
        acc_row8(acc, h + (size_t)s3 * D + col);
    }
    for (; j < cnt; j++) {
        int s = nbr[start + j];
        acc_row8(acc, h + (size_t)s * D + col);
    }

    float dd = dis[node];
    float4 b0 = *(const float4*)(bias + col);
    float4 b1 = *(const float4*)(bias + col + 4);
    float o[8];
    o[0] = fmaf(acc[0], dd, b0.x); o[1] = fmaf(acc[1], dd, b0.y);
    o[2] = fmaf(acc[2], dd, b0.z); o[3] = fmaf(acc[3], dd, b0.w);
    o[4] = fmaf(acc[4], dd, b1.x); o[5] = fmaf(acc[5], dd, b1.y);
    o[6] = fmaf(acc[6], dd, b1.z); o[7] = fmaf(acc[7], dd, b1.w);

    if (OUT_HALF) {
        __half2 p0 = __floats2half2_rn(o[0], o[1]);
        __half2 p1 = __floats2half2_rn(o[2], o[3]);
        __half2 p2 = __floats2half2_rn(o[4], o[5]);
        __half2 p3 = __floats2half2_rn(o[6], o[7]);
        uint4 pk = make_uint4(*(uint32_t*)&p0, *(uint32_t*)&p1,
                              *(uint32_t*)&p2, *(uint32_t*)&p3);
        *(uint4*)((__half*)y_out + (size_t)node * D + col) = pk;
    } else {
        float* yo = (float*)y_out + (size_t)node * D + col;
        *(float4*)yo = make_float4(o[0], o[1], o[2], o[3]);
        *(float4*)(yo + 4) = make_float4(o[4], o[5], o[6], o[7]);
    }
}

// ---------------------------------------------------------------------------
// host launcher
// ---------------------------------------------------------------------------
extern "C" void kernel_launch(void* const* d_in, const int* in_sizes, int n_in,
                              void* d_out, int out_size)
{
    const float* feat = (const float*)d_in[0];
    const int*   ei   = (const int*)d_in[1];
    const float* W0   = (const float*)d_in[2];
    const float* b0   = (const float*)d_in[3];
    const float* W1   = (const float*)d_in[4];
    const float* b1   = (const float*)d_in[5];
    const float* W2   = (const float*)d_in[6];
    const float* b2   = (const float*)d_in[7];
    float* out = (float*)d_out;

    const int n = in_sizes[0] / 128;
    const int E = in_sizes[1] / 2;
    const int* src = ei;
    const int* dst = ei + E;

    __half* h;  cudaGetSymbolAddress((void**)&h,   g_h);
    __half* y;  cudaGetSymbolAddress((void**)&y,   g_y);
    int*    deg; cudaGetSymbolAddress((void**)&deg, g_deg);
    float*  dis; cudaGetSymbolAddress((void**)&dis, g_dis);
    int*    offs;   cudaGetSymbolAddress((void**)&offs,   g_offs);
    int*    cursor; cudaGetSymbolAddress((void**)&cursor, g_cursor);
    int*    nbr;    cudaGetSymbolAddress((void**)&nbr,    g_nbr);
    int*    bsum;   cudaGetSymbolAddress((void**)&bsum,   g_bsum);

    const int T = 256;
    auto cdiv = [](int a, int b) { return (a + b - 1) / b; };
    const int nb = cdiv(n, 1024);

    // dynamic smem (halves): BM*40 + M*40
    const int smemA = (128 * 40 + 64 * 40) * 2;   // 15360 B (M=64)
    const int smemB = (128 * 40 + 32 * 40) * 2;   // 12800 B (M=32)

    // --- normalization + CSR build ---
    // Kernel order keeps gemm0 at launch index 3 (the ncu-profiled slot).
    cudaMemsetAsync(deg, 0, (size_t)n * sizeof(int));
    degree_kernel<<<cdiv(E, T), T>>>(dst, E, deg);                       // 0
    scan1_kernel<<<nb, 256>>>(deg, n, offs, bsum, dis);                  // 1
    scan3_kernel<<<cdiv(n, T), T>>>(offs, cursor, bsum, n, nb);          // 2

    // --- layer 0 GEMM (needs only dis): profiled slot ---
    gemm_f16<128, 64, false, float><<<cdiv(n, 128), 256, smemA>>>(feat, W0, dis, h, n);  // 3

    fill_kernel<<<cdiv(E, T), T>>>(src, dst, E, cursor, nbr);            // 4

    // --- layer 0 aggregate ---
    aggregate_kernel<64, true><<<cdiv(n * 8, T), T>>>(h, offs, deg, nbr, dis, b0, y, n);

    // --- layer 1: 64 -> 64 ---
    gemm_f16<64, 64, true, __half><<<cdiv(n, 128), 256, smemA>>>(y, W1, dis, h, n);
    aggregate_kernel<64, true><<<cdiv(n * 8, T), T>>>(h, offs, deg, nbr, dis, b1, y, n);

    // --- layer 2: 64 -> 32, direct fp32 to d_out ---
    gemm_f16<64, 32, true, __half><<<cdiv(n, 128), 256, smemB>>>(y, W2, dis, h, n);
    aggregate_kernel<32, false><<<cdiv(n * 4, T), T>>>(h, offs, deg, nbr, dis, b2, out, n);
}

// round 17
// speedup vs baseline: 1.4018x; 1.4018x over previous
#include <cuda_runtime.h>
#include <cuda_fp16.h>
#include <cstdint>

#define MAX_N 100000
#define MAX_E 1600000

// Scratch (device globals: no allocation allowed)
__device__ __half g_h[(size_t)MAX_N * 64];   // dis-scaled post-GEMM features (fp16)
__device__ __half g_y[(size_t)MAX_N * 64];   // aggregated features (fp16)
__device__ int    g_deg[MAX_N];              // in-degree (excl self loop)
__device__ float  g_dis[MAX_N];              // rsqrt(deg+1)
__device__ int    g_offs[MAX_N];             // CSR row offsets
__device__ int    g_cursor[MAX_N];           // fill cursors
__device__ int    g_nbr[MAX_E];              // src ids sorted by dst
__device__ int    g_bsum[256];               // block sums for scan

// ---------------------------------------------------------------------------
// degree
// ---------------------------------------------------------------------------
__global__ void degree_kernel(const int* __restrict__ dst, int E, int* __restrict__ deg) {
    int e = blockIdx.x * blockDim.x + threadIdx.x;
    if (e < E) atomicAdd(&deg[dst[e]], 1);
}

// ---------------------------------------------------------------------------
// prefix scan of deg -> offs (1024 elems / block), fused dis = rsqrt(deg+1)
// ---------------------------------------------------------------------------
__global__ __launch_bounds__(256)
void scan1_kernel(const int* __restrict__ deg, int n,
                  int* __restrict__ offs, int* __restrict__ bsum,
                  float* __restrict__ dis)
{
    __shared__ int warp_sums[8];
    const int base = blockIdx.x * 1024;
    const int tid = threadIdx.x;
    int v[4];
    int s = 0;
#pragma unroll
    for (int i = 0; i < 4; i++) {
        int idx = base + tid * 4 + i;
        v[i] = (idx < n) ? deg[idx] : 0;
        if (idx < n) dis[idx] = rsqrtf((float)v[i] + 1.0f);
        s += v[i];
    }
    const int lane = tid & 31, wid = tid >> 5;
    int ps = s;
#pragma unroll
    for (int d = 1; d < 32; d <<= 1) {
        int t = __shfl_up_sync(~0u, ps, d);
        if (lane >= d) ps += t;
    }
    if (lane == 31) warp_sums[wid] = ps;
    __syncthreads();
    if (tid < 8) {
        int w = warp_sums[tid];
#pragma unroll
        for (int d = 1; d < 8; d <<= 1) {
            int t = __shfl_up_sync(0xffu, w, d);
            if (tid >= d) w += t;
        }
        warp_sums[tid] = w;
    }
    __syncthreads();
    int thread_excl = (wid > 0 ? warp_sums[wid - 1] : 0) + (ps - s);
    int run = thread_excl;
#pragma unroll
    for (int i = 0; i < 4; i++) {
        int idx = base + tid * 4 + i;
        if (idx < n) offs[idx] = run;
        run += v[i];
    }
    if (tid == 255) bsum[blockIdx.x] = thread_excl + s;
}

// ---------------------------------------------------------------------------
// scan3: finalize offs/cursor (redundant per-block scan of <=128 block sums)
// ---------------------------------------------------------------------------
__global__ __launch_bounds__(256)
void scan3_kernel(int* __restrict__ offs, int* __restrict__ cursor,
                  const int* __restrict__ bsum, int n, int nb)
{
    __shared__ int sb[128];
    __shared__ int wsum[4];
    const int tid = threadIdx.x;

    int v = 0, ps = 0;
    const int lane = tid & 31, w = tid >> 5;
    if (tid < 128) {
        v = (tid < nb) ? bsum[tid] : 0;
        ps = v;
#pragma unroll
        for (int d = 1; d < 32; d <<= 1) {
            int t = __shfl_up_sync(~0u, ps, d);
            if (lane >= d) ps += t;
        }
        if (lane == 31) wsum[w] = ps;
    }
    __syncthreads();
    if (tid < 4) {
        int x = wsum[tid];
#pragma unroll
        for (int d = 1; d < 4; d <<= 1) {
            int t = __shfl_up_sync(0xfu, x, d);
            if (tid >= d) x += t;
        }
        wsum[tid] = x;
    }
    __syncthreads();
    if (tid < 128) {
        sb[tid] = (ps - v) + (w > 0 ? wsum[w - 1] : 0);   // exclusive prefix
    }
    __syncthreads();

    int i = blockIdx.x * blockDim.x + tid;
    if (i < n) {
        int o = offs[i] + sb[i >> 10];
        offs[i] = o;
        cursor[i] = o;
    }
}

__global__ void fill_kernel(const int* __restrict__ src, const int* __restrict__ dst,
                            int E, int* __restrict__ cursor, int* __restrict__ nbr)
{
    int e = blockIdx.x * blockDim.x + threadIdx.x;
    if (e < E) {
        int d = dst[e];
        int p = atomicAdd(&cursor[d], 1);
        nbr[p] = src[e];
    }
}

// ---------------------------------------------------------------------------
// FP16 tensor-core GEMM (mma.m16n8k16, fp32 accumulate), WHOLE-K staging:
// one stage phase, one sync, one mma phase — no chunk loop, latency paid once
// with high MLP. relu-on-load, dis-scale + fp16 epilogue.
// W staged fp16 TRANSPOSED (k-contig, stride K+8 halves -> conflict-free
// frag banks 4g+t).
// ---------------------------------------------------------------------------
__device__ __forceinline__ void mma_f16(float* c, const uint32_t* a,
                                        uint32_t b0, uint32_t b1) {
    asm volatile(
        "mma.sync.aligned.m16n8k16.row.col.f32.f16.f16.f32 "
        "{%0,%1,%2,%3}, {%4,%5,%6,%7}, {%8,%9}, {%0,%1,%2,%3};"
        : "+f"(c[0]), "+f"(c[1]), "+f"(c[2]), "+f"(c[3])
        : "r"(a[0]), "r"(a[1]), "r"(a[2]), "r"(a[3]), "r"(b0), "r"(b1));
}

template <int K, int M, bool RELU, typename XT>
__global__ __launch_bounds__(256)
void gemm_f16(const XT* __restrict__ X, const float* __restrict__ W,
              const float* __restrict__ dis, __half* __restrict__ H, int n)
{
    constexpr bool HALF_IN = (sizeof(XT) == 2);
    constexpr int BM = 128;
    constexpr int XSTR = K + 8;      // halves; (K+8)/2 b32 ≡ 4 mod 32
    constexpr int WTSTR = K + 8;
    constexpr int NB = M / 8;

    extern __shared__ __half smemh[];
    __half* xs = smemh;                     // BM * XSTR halves
    __half* wt = smemh + BM * XSTR;         // M * WTSTR halves (transposed W)

    const int tid  = threadIdx.x;
    const int lane = tid & 31;
    const int warp = tid >> 5;
    const int row0 = blockIdx.x * BM;
    const int wrow = warp * 16;
    const int g = lane >> 2;
    const int t = lane & 3;

    float acc[NB][4];
#pragma unroll
    for (int nb = 0; nb < NB; nb++)
#pragma unroll
        for (int c = 0; c < 4; c++) acc[nb][c] = 0.f;

    // --- stage the FULL X panel: BM rows x K cols ---
    if (HALF_IN) {
        // K halves per row; uint4 = 8 halves. total BM*K/8 uint4s.
        constexpr int NLD = BM * K / 8 / 256;     // 4 for K=64
        const __half2 z2 = __floats2half2_rn(0.f, 0.f);
#pragma unroll
        for (int it = 0; it < NLD; it++) {
            int i = it * 256 + tid;
            int row = i / (K / 8);
            int c8 = i % (K / 8);
            int grow = row0 + row;
            uint4 raw = make_uint4(0u, 0u, 0u, 0u);
            if (grow < n)
                raw = *(const uint4*)((const __half*)X + (size_t)grow * K + c8 * 8);
            if (RELU) {
                __half2* h2 = (__half2*)&raw;
#pragma unroll
                for (int q = 0; q < 4; q++) h2[q] = __hmax2(h2[q], z2);
            }
            *(uint4*)&xs[row * XSTR + c8 * 8] = raw;
        }
    } else {
        // K floats per row; float4 = 4 floats. total BM*K/4 float4s.
        constexpr int NLD = BM * K / 4 / 256;     // 16 for K=128
#pragma unroll
        for (int it = 0; it < NLD; it++) {
            int i = it * 256 + tid;
            int row = i / (K / 4);
            int c4 = i % (K / 4);
            int grow = row0 + row;
            float4 v = make_float4(0.f, 0.f, 0.f, 0.f);
            if (grow < n)
                v = *(const float4*)((const float*)X + (size_t)grow * K + c4 * 4);
            if (RELU) {
                v.x = fmaxf(v.x, 0.f); v.y = fmaxf(v.y, 0.f);
                v.z = fmaxf(v.z, 0.f); v.w = fmaxf(v.w, 0.f);
            }
            __half2 p0 = __floats2half2_rn(v.x, v.y);
            __half2 p1 = __floats2half2_rn(v.z, v.w);
            uint2 pk = make_uint2(*(uint32_t*)&p0, *(uint32_t*)&p1);
            *(uint2*)&xs[row * XSTR + c4 * 4] = pk;
        }
    }
    // --- stage the FULL W panel TRANSPOSED: wt[m][k] = fp16(W[k][m]) ---
#pragma unroll
    for (int i = tid * 4; i < K * M; i += 1024) {
        int kk = i / M, m = i % M;
        float4 v = *(const float4*)(W + (size_t)kk * M + m);
        wt[(m + 0) * WTSTR + kk] = __float2half_rn(v.x);
        wt[(m + 1) * WTSTR + kk] = __float2half_rn(v.y);
        wt[(m + 2) * WTSTR + kk] = __float2half_rn(v.z);
        wt[(m + 3) * WTSTR + kk] = __float2half_rn(v.w);
    }
    __syncthreads();

    // --- mma phase over the whole K ---
#pragma unroll
    for (int ks = 0; ks < K / 16; ks++) {
        const uint32_t* xp = (const uint32_t*)xs;
        const uint32_t* wp = (const uint32_t*)wt;
        uint32_t a[4];
        {
            int ib = (wrow + g) * (XSTR / 2) + ks * 8 + t;
            a[0] = xp[ib];
            a[1] = xp[ib + 8 * (XSTR / 2)];
            a[2] = xp[ib + 4];
            a[3] = xp[ib + 8 * (XSTR / 2) + 4];
        }
#pragma unroll
        for (int nb = 0; nb < NB; nb++) {
            const int nn = nb * 8 + g;
            int jb = nn * (WTSTR / 2) + ks * 8 + t;
            uint32_t b0 = wp[jb];
            uint32_t b1 = wp[jb + 4];
            mma_f16(acc[nb], a, b0, b1);
        }
    }

    // epilogue: scale by dis[row], convert fp16, store
    const int rA = row0 + wrow + g;
    const int rB = rA + 8;
    const float sA = (rA < n) ? dis[rA] : 0.f;
    const float sB = (rB < n) ? dis[rB] : 0.f;
#pragma unroll
    for (int nb = 0; nb < NB; nb++) {
        int colo = nb * 8 + 2 * t;
        if (rA < n) {
            __half2 p = __floats2half2_rn(acc[nb][0] * sA, acc[nb][1] * sA);
            *(__half2*)(H + (size_t)rA * M + colo) = p;
        }
        if (rB < n) {
            __half2 p = __floats2half2_rn(acc[nb][2] * sB, acc[nb][3] * sB);
            *(__half2*)(H + (size_t)rB * M + colo) = p;
        }
    }
}

// ---------------------------------------------------------------------------
// pull-style CSR aggregation (fp16 gather, fp32 accumulate):
//   y[d,:] = dis[d] * ( h[d,:] + sum_{s in N(d)} h[s,:] ) + b[:]
// D/8 threads per node; 4-deep neighbor unroll (proven best: R9)
// ---------------------------------------------------------------------------
__device__ __forceinline__ void acc_row8(float* acc, const __half* p) {
    uint4 raw = *(const uint4*)p;
    const __half2* h2 = (const __half2*)&raw;
#pragma unroll
    for (int q = 0; q < 4; q++) {
        float2 f = __half22float2(h2[q]);
        acc[q * 2 + 0] += f.x;
        acc[q * 2 + 1] += f.y;
    }
}

template <int D, bool OUT_HALF>
__global__ __launch_bounds__(256)
void aggregate_kernel(const __half* __restrict__ h,
                      const int* __restrict__ offs,
                      const int* __restrict__ deg,
                      const int* __restrict__ nbr,
                      const float* __restrict__ dis,
                      const float* __restrict__ bias,
                      void* __restrict__ y_out, int n)
{
    constexpr int TPN = D / 8;
    int gid = blockIdx.x * blockDim.x + threadIdx.x;
    int node = gid / TPN;
    int lane = gid % TPN;
    if (node >= n) return;
    const int col = lane * 8;
    const int start = offs[node];
    const int cnt = deg[node];

    float acc[8];
    {
        uint4 raw = *(const uint4*)(h + (size_t)node * D + col);
        const __half2* h2 = (const __half2*)&raw;
#pragma unroll
        for (int q = 0; q < 4; q++) {
            float2 f = __half22float2(h2[q]);
            acc[q * 2 + 0] = f.x;
            acc[q * 2 + 1] = f.y;
        }
    }

    int j = 0;
    for (; j + 4 <= cnt; j += 4) {
        int s0 = nbr[start + j + 0];
        int s1 = nbr[start + j + 1];
        int s2 = nbr[start + j + 2];
        int s3 = nbr[start + j + 3];
        acc_row8(acc, h + (size_t)s0 * D + col);
        acc_row8(acc, h + (size_t)s1 * D + col);
        acc_row8(acc, h + (size_t)s2 * D + col);
        acc_row8(acc, h + (size_t)s3 * D + col);
    }
    for (; j < cnt; j++) {
        int s = nbr[start + j];
        acc_row8(acc, h + (size_t)s * D + col);
    }

    float dd = dis[node];
    float4 b0 = *(const float4*)(bias + col);
    float4 b1 = *(const float4*)(bias + col + 4);
    float o[8];
    o[0] = fmaf(acc[0], dd, b0.x); o[1] = fmaf(acc[1], dd, b0.y);
    o[2] = fmaf(acc[2], dd, b0.z); o[3] = fmaf(acc[3], dd, b0.w);
    o[4] = fmaf(acc[4], dd, b1.x); o[5] = fmaf(acc[5], dd, b1.y);
    o[6] = fmaf(acc[6], dd, b1.z); o[7] = fmaf(acc[7], dd, b1.w);

    if (OUT_HALF) {
        __half2 p0 = __floats2half2_rn(o[0], o[1]);
        __half2 p1 = __floats2half2_rn(o[2], o[3]);
        __half2 p2 = __floats2half2_rn(o[4], o[5]);
        __half2 p3 = __floats2half2_rn(o[6], o[7]);
        uint4 pk = make_uint4(*(uint32_t*)&p0, *(uint32_t*)&p1,
                              *(uint32_t*)&p2, *(uint32_t*)&p3);
        *(uint4*)((__half*)y_out + (size_t)node * D + col) = pk;
    } else {
        float* yo = (float*)y_out + (size_t)node * D + col;
        *(float4*)yo = make_float4(o[0], o[1], o[2], o[3]);
        *(float4*)(yo + 4) = make_float4(o[4], o[5], o[6], o[7]);
    }
}

// ---------------------------------------------------------------------------
// host launcher
// ---------------------------------------------------------------------------
extern "C" void kernel_launch(void* const* d_in, const int* in_sizes, int n_in,
                              void* d_out, int out_size)
{
    const float* feat = (const float*)d_in[0];
    const int*   ei   = (const int*)d_in[1];
    const float* W0   = (const float*)d_in[2];
    const float* b0   = (const float*)d_in[3];
    const float* W1   = (const float*)d_in[4];
    const float* b1   = (const float*)d_in[5];
    const float* W2   = (const float*)d_in[6];
    const float* b2   = (const float*)d_in[7];
    float* out = (float*)d_out;

    const int n = in_sizes[0] / 128;
    const int E = in_sizes[1] / 2;
    const int* src = ei;
    const int* dst = ei + E;

    __half* h;  cudaGetSymbolAddress((void**)&h,   g_h);
    __half* y;  cudaGetSymbolAddress((void**)&y,   g_y);
    int*    deg; cudaGetSymbolAddress((void**)&deg, g_deg);
    float*  dis; cudaGetSymbolAddress((void**)&dis, g_dis);
    int*    offs;   cudaGetSymbolAddress((void**)&offs,   g_offs);
    int*    cursor; cudaGetSymbolAddress((void**)&cursor, g_cursor);
    int*    nbr;    cudaGetSymbolAddress((void**)&nbr,    g_nbr);
    int*    bsum;   cudaGetSymbolAddress((void**)&bsum,   g_bsum);

    const int T = 256;
    auto cdiv = [](int a, int b) { return (a + b - 1) / b; };
    const int nb = cdiv(n, 1024);

    // dynamic smem (bytes): (BM + M) * (K+8) halves
    const int smem0 = (128 + 64) * (128 + 8) * 2;   // 52224 (K=128, M=64)
    const int smem1 = (128 + 64) * (64 + 8) * 2;    // 27648 (K=64,  M=64)
    const int smem2 = (128 + 32) * (64 + 8) * 2;    // 23040 (K=64,  M=32)
    cudaFuncSetAttribute((const void*)gemm_f16<128, 64, false, float>,
                         cudaFuncAttributeMaxDynamicSharedMemorySize, smem0);

    // --- normalization + CSR build ---
    // Kernel order keeps gemm0 at launch index 3 (the ncu-profiled slot).
    cudaMemsetAsync(deg, 0, (size_t)n * sizeof(int));
    degree_kernel<<<cdiv(E, T), T>>>(dst, E, deg);                       // 0
    scan1_kernel<<<nb, 256>>>(deg, n, offs, bsum, dis);                  // 1
    scan3_kernel<<<cdiv(n, T), T>>>(offs, cursor, bsum, n, nb);          // 2

    // --- layer 0 GEMM (needs only dis): profiled slot ---
    gemm_f16<128, 64, false, float><<<cdiv(n, 128), 256, smem0>>>(feat, W0, dis, h, n);  // 3

    fill_kernel<<<cdiv(E, T), T>>>(src, dst, E, cursor, nbr);            // 4

    // --- layer 0 aggregate ---
    aggregate_kernel<64, true><<<cdiv(n * 8, T), T>>>(h, offs, deg, nbr, dis, b0, y, n);

    // --- layer 1: 64 -> 64 ---
    gemm_f16<64, 64, true, __half><<<cdiv(n, 128), 256, smem1>>>(y, W1, dis, h, n);
    aggregate_kernel<64, true><<<cdiv(n * 8, T), T>>>(h, offs, deg, nbr, dis, b1, y, n);

    // --- layer 2: 64 -> 32, direct fp32 to d_out ---
    gemm_f16<64, 32, true, __half><<<cdiv(n, 128), 256, smem2>>>(y, W2, dis, h, n);
    aggregate_kernel<32, false><<<cdiv(n * 4, T), T>>>(h, offs, deg, nbr, dis, b2, out, n);
}